// round 9
// baseline (speedup 1.0000x reference)
#include <cuda_runtime.h>
#include <cuda_bf16.h>
#include <stdint.h>

// Problem constants (fixed shapes for this problem)
#define DIMN   256
#define HISTN  200
#define BATCHN 2048
#define VROWS  100000

// ---------------- scratch (device globals; no allocation allowed) ----------------
__device__ float g_VW[(size_t)VROWS * DIMN];   // venue_emb @ W1, fp32
__device__ float g_C[HISTN * DIMN];            // P@W2 + bias
__device__ float g_scale[VROWS];               // min(1, 1/max(||row||, eps))

// ---------------- helpers ----------------
__device__ __forceinline__ float tanh_fast(float x) {
    float y;
    asm("tanh.approx.f32 %0, %1;" : "=f"(y) : "f"(x));
    return y;
}

__device__ __forceinline__ void mma16816(float* c,
                                         uint32_t a0, uint32_t a1, uint32_t a2, uint32_t a3,
                                         uint32_t b0, uint32_t b1) {
    asm volatile(
        "mma.sync.aligned.m16n8k16.row.col.f32.bf16.bf16.f32 "
        "{%0,%1,%2,%3},{%4,%5,%6,%7},{%8,%9},{%0,%1,%2,%3};\n"
        : "+f"(c[0]), "+f"(c[1]), "+f"(c[2]), "+f"(c[3])
        : "r"(a0), "r"(a1), "r"(a2), "r"(a3), "r"(b0), "r"(b1));
}

// ---------------- K1: C = P @ W2 + bias  [200,256] ----------------
__global__ void k_prec_C(const float* __restrict__ P,
                         const float* __restrict__ W2,
                         const float* __restrict__ bias) {
    __shared__ float sp[DIMN];
    int h = blockIdx.x;
    int e = threadIdx.x;
    sp[e] = P[h * DIMN + e];
    __syncthreads();
    float acc = bias[h * DIMN + e];
#pragma unroll 16
    for (int d = 0; d < DIMN; d++)
        acc = fmaf(sp[d], W2[d * DIMN + e], acc);
    g_C[h * DIMN + e] = acc;
}

// ---------------- K2: per-row venue scales ----------------
__global__ void k_scales(const float* __restrict__ venue, int V) {
    int warp = threadIdx.x >> 5, lane = threadIdx.x & 31;
    int row = blockIdx.x * 8 + warp;
    if (row >= V) return;
    const float4* r = reinterpret_cast<const float4*>(venue + (size_t)row * DIMN);
    float s = 0.f;
#pragma unroll
    for (int i = 0; i < 2; i++) {
        float4 v = r[lane + i * 32];
        s += v.x * v.x + v.y * v.y + v.z * v.z + v.w * v.w;
    }
#pragma unroll
    for (int o = 16; o; o >>= 1) s += __shfl_xor_sync(0xffffffffu, s, o);
    if (lane == 0) {
        float n = sqrtf(s);
        g_scale[row] = fminf(1.f, 1.f / fmaxf(n, 1e-12f));
    }
}

// ---------------- K3: VW = venue_emb @ W1  (bf16 mma, fp32 accum) ----------------
// CTA tile 128(M) x 128(N), 8 warps (4x2), warp tile 32x64, K chunks of 16.
#define SA 24   // smem row stride (bf16 elems) -> conflict-free for frag loads

__device__ __forceinline__ void k3_load_chunk(const float* __restrict__ A,
                                              const float* __restrict__ Bw,
                                              int M, int m0, int n0, int kc, int tid,
                                              float4* ra, float4* rb) {
    int kbase = kc * 16;
#pragma unroll
    for (int i = 0; i < 2; i++) {
        int idx = tid + i * 256;
        int ar = idx >> 2, ac4 = idx & 3;
        int grow = m0 + ar;
        if (grow < M)
            ra[i] = *(reinterpret_cast<const float4*>(A + (size_t)grow * DIMN + kbase) + ac4);
        else
            ra[i] = make_float4(0.f, 0.f, 0.f, 0.f);
        int bk = idx >> 5, bn4 = idx & 31;
        rb[i] = *(reinterpret_cast<const float4*>(Bw + (size_t)(kbase + bk) * DIMN + n0) + bn4);
    }
}

__global__ __launch_bounds__(256, 2)
void k_gemm_vw(const float* __restrict__ A, const float* __restrict__ Bw, int M) {
    __shared__ __align__(16) __nv_bfloat16 As[128 * SA];  // [row][k] stride SA
    __shared__ __align__(16) __nv_bfloat16 Bs[128 * SA];  // [n][k]  stride SA (transposed W1 chunk)

    int tid  = threadIdx.x;
    int warp = tid >> 5, lane = tid & 31;
    int g = lane >> 2, tg = lane & 3;
    int wm = warp >> 1, wn = warp & 1;
    int m0 = blockIdx.x * 128;
    int n0 = blockIdx.y * 128;

    float c[2][8][4];
#pragma unroll
    for (int mt = 0; mt < 2; mt++)
#pragma unroll
        for (int nt = 0; nt < 8; nt++)
#pragma unroll
            for (int j = 0; j < 4; j++) c[mt][nt][j] = 0.f;

    float4 ra[2], rb[2];
    k3_load_chunk(A, Bw, M, m0, n0, 0, tid, ra, rb);

    for (int kc = 0; kc < 16; kc++) {
        // stage registers -> smem (bf16)
#pragma unroll
        for (int i = 0; i < 2; i++) {
            int idx = tid + i * 256;
            int ar = idx >> 2, ac = (idx & 3) * 4;
            __nv_bfloat162 p01 = __floats2bfloat162_rn(ra[i].x, ra[i].y);
            __nv_bfloat162 p23 = __floats2bfloat162_rn(ra[i].z, ra[i].w);
            *reinterpret_cast<__nv_bfloat162*>(&As[ar * SA + ac])     = p01;
            *reinterpret_cast<__nv_bfloat162*>(&As[ar * SA + ac + 2]) = p23;
            int bk = idx >> 5, bn = (idx & 31) * 4;
            Bs[(bn + 0) * SA + bk] = __float2bfloat16_rn(rb[i].x);
            Bs[(bn + 1) * SA + bk] = __float2bfloat16_rn(rb[i].y);
            Bs[(bn + 2) * SA + bk] = __float2bfloat16_rn(rb[i].z);
            Bs[(bn + 3) * SA + bk] = __float2bfloat16_rn(rb[i].w);
        }
        __syncthreads();

        if (kc < 15) k3_load_chunk(A, Bw, M, m0, n0, kc + 1, tid, ra, rb);

#pragma unroll
        for (int mt = 0; mt < 2; mt++) {
            int row = wm * 32 + mt * 16 + g;
            uint32_t a0 = *reinterpret_cast<const uint32_t*>(&As[row * SA + 2 * tg]);
            uint32_t a1 = *reinterpret_cast<const uint32_t*>(&As[(row + 8) * SA + 2 * tg]);
            uint32_t a2 = *reinterpret_cast<const uint32_t*>(&As[row * SA + 2 * tg + 8]);
            uint32_t a3 = *reinterpret_cast<const uint32_t*>(&As[(row + 8) * SA + 2 * tg + 8]);
#pragma unroll
            for (int nt = 0; nt < 8; nt++) {
                int nn = wn * 64 + nt * 8 + g;
                uint32_t b0 = *reinterpret_cast<const uint32_t*>(&Bs[nn * SA + 2 * tg]);
                uint32_t b1 = *reinterpret_cast<const uint32_t*>(&Bs[nn * SA + 2 * tg + 8]);
                mma16816(c[mt][nt], a0, a1, a2, a3, b0, b1);
            }
        }
        __syncthreads();
    }

    // store D tiles
#pragma unroll
    for (int mt = 0; mt < 2; mt++) {
#pragma unroll
        for (int nt = 0; nt < 8; nt++) {
            int row = m0 + wm * 32 + mt * 16 + g;
            int col = n0 + wn * 64 + nt * 8 + 2 * tg;
            if (row < M) {
                float2 v0 = make_float2(c[mt][nt][0], c[mt][nt][1]);
                *reinterpret_cast<float2*>(&g_VW[(size_t)row * DIMN + col]) = v0;
            }
            if (row + 8 < M) {
                float2 v1 = make_float2(c[mt][nt][2], c[mt][nt][3]);
                *reinterpret_cast<float2*>(&g_VW[(size_t)(row + 8) * DIMN + col]) = v1;
            }
        }
    }
}

// ---------------- K4: fused attention-pool + TransE score ----------------
// One CTA per batch element; 128 threads; thread t owns columns {2t, 2t+1}.
__device__ __forceinline__ float block_sum(float v, volatile float* red) {
#pragma unroll
    for (int o = 16; o; o >>= 1) v += __shfl_xor_sync(0xffffffffu, v, o);
    __syncthreads();  // protect prior reads of red
    if ((threadIdx.x & 31) == 0) red[threadIdx.x >> 5] = v;
    __syncthreads();
    return red[0] + red[1] + red[2] + red[3];
}

__global__ __launch_bounds__(128)
void k_score(const int* __restrict__ bu, const int* __restrict__ bv,
             const int* __restrict__ bh,
             const float* __restrict__ user, const float* __restrict__ venue,
             const float* __restrict__ aptr, float* __restrict__ out) {
    __shared__ int   idx_s[HISTN];
    __shared__ float sc_s[HISTN];
    __shared__ float red[4];

    int b = blockIdx.x;
    int t = threadIdx.x;

    const int* hrow = bh + (size_t)b * HISTN;
    for (int i = t; i < HISTN; i += 128) {
        int vi = hrow[i];
        idx_s[i] = vi;
        sc_s[i]  = g_scale[vi];
    }
    __syncthreads();

    const float a = aptr[0];
    float nx = 0.f, ny = 0.f, dx = 0.f, dy = 0.f;

#pragma unroll 4
    for (int h = 0; h < HISTN; h++) {
        int   vi = idx_s[h];
        float sc = sc_s[h];
        float2 w  = *(reinterpret_cast<const float2*>(g_VW   + (size_t)vi * DIMN) + t);
        float2 hv = *(reinterpret_cast<const float2*>(venue  + (size_t)vi * DIMN) + t);
        float2 cc = *(reinterpret_cast<const float2*>(g_C + h * DIMN) + t);
        float z0 = fmaf(sc, w.x, cc.x);
        float z1 = fmaf(sc, w.y, cc.y);
        float p0 = __expf(tanh_fast(z0));   // tanh in (-1,1): no max-sub needed
        float p1 = __expf(tanh_fast(z1));
        dx += p0;  dy += p1;
        nx = fmaf(p0 * sc, hv.x, nx);
        ny = fmaf(p1 * sc, hv.y, ny);
    }

    float lx = nx / dx + a;
    float ly = ny / dy + a;

    float2 uu = *(reinterpret_cast<const float2*>(user  + (size_t)bu[b] * DIMN) + t);
    float2 vv = *(reinterpret_cast<const float2*>(venue + (size_t)bv[b] * DIMN) + t);

    float su = block_sum(uu.x * uu.x + uu.y * uu.y, red);
    float sv = block_sum(vv.x * vv.x + vv.y * vv.y, red);
    float sl = block_sum(lx * lx + ly * ly, red);

    float iu = 1.f / fmaxf(sqrtf(su), 1e-12f);
    float iv = 1.f / fmaxf(sqrtf(sv), 1e-12f);
    float il = 1.f / fmaxf(sqrtf(sl), 1e-12f);

    float sx = uu.x * iu + lx * il - vv.x * iv;
    float sy = uu.y * iu + ly * il - vv.y * iv;

    float ss = block_sum(sx * sx + sy * sy, red);
    if (t == 0) out[b] = sqrtf(ss);
}

// ---------------- launch ----------------
extern "C" void kernel_launch(void* const* d_in, const int* in_sizes, int n_in,
                              void* d_out, int out_size) {
    const int*   batch_u  = (const int*)d_in[0];
    const int*   batch_v  = (const int*)d_in[1];
    const int*   batch_h  = (const int*)d_in[2];
    // d_in[3], d_in[4]: batch_olc / batch_cluster_olc — unused by the model
    const float* user_emb  = (const float*)d_in[5];
    const float* venue_emb = (const float*)d_in[6];
    const float* W1        = (const float*)d_in[7];
    const float* W2        = (const float*)d_in[8];
    const float* P         = (const float*)d_in[9];
    const float* bias      = (const float*)d_in[10];
    const float* a         = (const float*)d_in[11];
    float* out = (float*)d_out;

    int B = in_sizes[0];
    int V = in_sizes[6] / DIMN;
    if (V > VROWS) V = VROWS;  // scratch sized for the fixed problem

    // K1: C = P@W2 + bias
    k_prec_C<<<HISTN, DIMN>>>(P, W2, bias);

    // K2: venue row scales
    k_scales<<<(V + 7) / 8, 256>>>(venue_emb, V);

    // K3: VW = venue_emb @ W1 (bf16 mma)
    dim3 g3((V + 127) / 128, DIMN / 128);
    k_gemm_vw<<<g3, 256>>>(venue_emb, W1, V);

    // K4: fused score
    k_score<<<B, 128>>>(batch_u, batch_v, batch_h, user_emb, venue_emb, a, out);
}